// round 9
// baseline (speedup 1.0000x reference)
#include <cuda_runtime.h>
#include <cuda_fp16.h>
#include <mma.h>
#include <math.h>

using namespace nvcuda;

#define NN   50000
#define EE   1600000
#define ET   (EE + NN)
#define INC  256
#define HC   128
#define HH   4
#define CC   32
#define OUTC 64
#define SCAN_BLKS ((NN + 255) / 256)   // 196
#define AGG_BLKS  625

// ---------------- scratch (device globals) ------------------------------------
__device__ __align__(16) __half g_xh[(size_t)NN * INC];     // 25.6 MB fp16 x
__device__ __align__(16) __half g_wh[(size_t)INC * HC];     // 64 KB fp16 W
__device__ __align__(16) __half g_hh[(size_t)NN * HC];      // 12.8 MB fp16 h
__device__ __align__(16) float g_asrc[(size_t)NN * HH];
__device__ __align__(16) float g_adst[(size_t)NN * HH];
__device__            int   g_deg[NN];
__device__            int   g_off[NN + 1];
__device__            int   g_cur[NN];
__device__            int   g_bsum[SCAN_BLKS];
__device__            int   g_csr[ET];                       // 6.6 MB

// ---------------- helpers ----------------------------------------------------
__device__ __forceinline__ float leaky(float v) {
    return v >= 0.0f ? v : 0.2f * v;
}
__device__ __forceinline__ int clampN(int v) {
    return v < 0 ? 0 : (v >= NN ? NN - 1 : v);
}

// ---------------- tiny init ---------------------------------------------------
__global__ void k_initdeg() {
    int i = blockIdx.x * blockDim.x + threadIdx.x;
    if (i < NN) g_deg[i] = 1;
}

// ---------------- histogram of destinations -----------------------------------
__global__ void k_hist(const int* __restrict__ ei) {
    int i = blockIdx.x * blockDim.x + threadIdx.x;
    if (i >= EE) return;
    atomicAdd(&g_deg[clampN(ei[EE + i])], 1);
}

// ---------------- K0: x,W fp32 -> fp16 ----------------------------------------
__global__ void k_cvt(const float* __restrict__ x, const float* __restrict__ W) {
    int i = blockIdx.x * blockDim.x + threadIdx.x;     // one per 8 elems
    if (i < NN * INC / 8) {
        float4 a = *(const float4*)&x[(size_t)i * 8];
        float4 b = *(const float4*)&x[(size_t)i * 8 + 4];
        __half2 h0 = __floats2half2_rn(a.x, a.y);
        __half2 h1 = __floats2half2_rn(a.z, a.w);
        __half2 h2 = __floats2half2_rn(b.x, b.y);
        __half2 h3 = __floats2half2_rn(b.z, b.w);
        uint4 v;
        v.x = *(unsigned*)&h0; v.y = *(unsigned*)&h1;
        v.z = *(unsigned*)&h2; v.w = *(unsigned*)&h3;
        *(uint4*)&g_xh[(size_t)i * 8] = v;
    }
    if (i < INC * HC / 8) {
        float4 a = *(const float4*)&W[(size_t)i * 8];
        float4 b = *(const float4*)&W[(size_t)i * 8 + 4];
        __half2 h0 = __floats2half2_rn(a.x, a.y);
        __half2 h1 = __floats2half2_rn(a.z, a.w);
        __half2 h2 = __floats2half2_rn(b.x, b.y);
        __half2 h3 = __floats2half2_rn(b.z, b.w);
        uint4 v;
        v.x = *(unsigned*)&h0; v.y = *(unsigned*)&h1;
        v.z = *(unsigned*)&h2; v.w = *(unsigned*)&h3;
        *(uint4*)&g_wh[(size_t)i * 8] = v;
    }
}

// ---------------- K1: h = x @ W via WMMA + fused attention --------------------
// 256 threads (8 warps). Block tile: 128 rows. Warp strip: 16 rows x 128 cols.
// K-chunk 32 (2 k-steps per sync).
__global__ void __launch_bounds__(256) k_gemm1t(
        const float* __restrict__ att_src, const float* __restrict__ att_dst) {
    __shared__ __half xs[128][32];          // 8 KB
    __shared__ __half wsb[32][128];         // 8 KB
    __shared__ float  stage[8][16][20];     // 10 KB (ldm=20, mult of 4)

    const int t    = threadIdx.x;
    const int warp = t >> 5;
    const int lane = t & 31;
    const int row0 = blockIdx.x * 128;
    const int wrow = row0 + warp * 16;

    wmma::fragment<wmma::accumulator, 16, 16, 16, float> acc[8];
#pragma unroll
    for (int j = 0; j < 8; j++) wmma::fill_fragment(acc[j], 0.0f);

    for (int kt = 0; kt < 8; kt++) {
        // x tile: 128 rows x 32 halves. 2 threads/row, 16 halves (2x uint4) each.
        {
            int r  = t >> 1;
            int hp = t & 1;
            int gr = row0 + r; if (gr >= NN) gr = NN - 1;
            const __half* src = &g_xh[(size_t)gr * INC + kt * 32 + hp * 16];
            *(uint4*)&xs[r][hp * 16]     = *(const uint4*)&src[0];
            *(uint4*)&xs[r][hp * 16 + 8] = *(const uint4*)&src[8];
        }
        // W tile: 32 k x 128 halves = 512 uint4; 2 per thread.
#pragma unroll
        for (int u = 0; u < 2; u++) {
            int id = t + u * 256;
            int rr = id >> 4;
            int c8 = id & 15;
            *(uint4*)&wsb[rr][c8 * 8] =
                *(const uint4*)&g_wh[(size_t)(kt * 32 + rr) * HC + c8 * 8];
        }
        __syncthreads();

#pragma unroll
        for (int ks = 0; ks < 2; ks++) {
            wmma::fragment<wmma::matrix_a, 16, 16, 16, __half, wmma::row_major> af;
            wmma::load_matrix_sync(af, &xs[warp * 16][ks * 16], 32);
#pragma unroll
            for (int j = 0; j < 8; j++) {
                wmma::fragment<wmma::matrix_b, 16, 16, 16, __half, wmma::row_major> bf;
                wmma::load_matrix_sync(bf, &wsb[ks * 16][j * 16], 128);
                wmma::mma_sync(acc[j], af, bf, acc[j]);
            }
        }
        __syncthreads();
    }

    // Epilogue: per 16-col tile, stage fp32 -> (attention partial, fp16 h store)
    const int lrow = lane >> 1;
    const int lhp  = lane & 1;
    const int grow = wrow + lrow;
    float sS[4] = {0.f, 0.f, 0.f, 0.f};
    float sD[4] = {0.f, 0.f, 0.f, 0.f};

#pragma unroll
    for (int j = 0; j < 8; j++) {
        wmma::store_matrix_sync(&stage[warp][0][0], acc[j], 20, wmma::mem_row_major);
        __syncwarp();
        int c8 = j * 2 + lhp;
        int hd = c8 >> 2;
        const float* sp = &stage[warp][lrow][lhp * 8];
        float4 v0 = make_float4(sp[0], sp[1], sp[2], sp[3]);
        float4 v1 = make_float4(sp[4], sp[5], sp[6], sp[7]);
        float4 aS0 = *(const float4*)&att_src[c8 * 8];
        float4 aS1 = *(const float4*)&att_src[c8 * 8 + 4];
        float4 aD0 = *(const float4*)&att_dst[c8 * 8];
        float4 aD1 = *(const float4*)&att_dst[c8 * 8 + 4];
        sS[hd] += v0.x * aS0.x + v0.y * aS0.y + v0.z * aS0.z + v0.w * aS0.w
                + v1.x * aS1.x + v1.y * aS1.y + v1.z * aS1.z + v1.w * aS1.w;
        sD[hd] += v0.x * aD0.x + v0.y * aD0.y + v0.z * aD0.z + v0.w * aD0.w
                + v1.x * aD1.x + v1.y * aD1.y + v1.z * aD1.z + v1.w * aD1.w;
        if (grow < NN) {
            __half2 p0 = __floats2half2_rn(v0.x, v0.y);
            __half2 p1 = __floats2half2_rn(v0.z, v0.w);
            __half2 p2 = __floats2half2_rn(v1.x, v1.y);
            __half2 p3 = __floats2half2_rn(v1.z, v1.w);
            uint4 pv;
            pv.x = *(unsigned*)&p0; pv.y = *(unsigned*)&p1;
            pv.z = *(unsigned*)&p2; pv.w = *(unsigned*)&p3;
            *(uint4*)&g_hh[(size_t)grow * HC + c8 * 8] = pv;
        }
        __syncwarp();
    }
    const unsigned FULL = 0xffffffffu;
#pragma unroll
    for (int hd = 0; hd < 4; hd++) {
        sS[hd] += __shfl_xor_sync(FULL, sS[hd], 1);
        sD[hd] += __shfl_xor_sync(FULL, sD[hd], 1);
    }
    if (lhp == 0 && grow < NN) {
        float4 vs = make_float4(sS[0], sS[1], sS[2], sS[3]);
        float4 vd = make_float4(sD[0], sD[1], sD[2], sD[3]);
        *(float4*)&g_asrc[(size_t)grow * 4] = vs;
        *(float4*)&g_adst[(size_t)grow * 4] = vd;
    }
}

// ---------------- CSR scan / prep / scatter -----------------------------------
__global__ void k_scanA() {
    __shared__ int sh[256];
    int t = threadIdx.x;
    int idx = blockIdx.x * 256 + t;
    int v = (idx < NN) ? g_deg[idx] : 0;
    sh[t] = v;
    __syncthreads();
#pragma unroll
    for (int o = 1; o < 256; o <<= 1) {
        int u = (t >= o) ? sh[t - o] : 0;
        __syncthreads();
        sh[t] += u;
        __syncthreads();
    }
    if (idx < NN) g_off[idx] = sh[t] - v;
    if (t == 255) g_bsum[blockIdx.x] = sh[255];
}

__global__ void k_scanB() {
    __shared__ int sh[SCAN_BLKS];
    int t = threadIdx.x;
    int v = (t < SCAN_BLKS) ? g_bsum[t] : 0;
    if (t < SCAN_BLKS) sh[t] = v;
    __syncthreads();
    for (int o = 1; o < SCAN_BLKS; o <<= 1) {
        int u = (t >= o && t < SCAN_BLKS) ? sh[t - o] : 0;
        __syncthreads();
        if (t < SCAN_BLKS) sh[t] += u;
        __syncthreads();
    }
    if (t < SCAN_BLKS) g_bsum[t] = sh[t] - v;
}

__global__ void k_prep() {
    int n = blockIdx.x * blockDim.x + threadIdx.x;
    if (n >= NN) return;
    int off = g_off[n] + g_bsum[n >> 8];
    g_off[n] = off;
    g_csr[off] = n;          // self loop first
    g_cur[n] = off + 1;
    if (n == 0) g_off[NN] = ET;
}

__global__ void k_scatter(const int* __restrict__ ei) {
    int i = blockIdx.x * blockDim.x + threadIdx.x;
    if (i >= EE) return;
    int s = clampN(ei[i]);
    int d = clampN(ei[EE + i]);
    int pos = atomicAdd(&g_cur[d], 1);
    g_csr[pos] = s;
}

// ---------------- K6: softmax + aggregation + ELU + output GEMV (fused) -------
__global__ void __launch_bounds__(256) k_aggrout(
        const float* __restrict__ bias, const float* __restrict__ lin_W,
        const float* __restrict__ lin_b, float* __restrict__ out) {
    __shared__ float ws[HC * OUTC];     // 32 KB
    __shared__ float stg[8][HC];        // 4 KB per-warp row staging
    __shared__ float bs[HC];
    __shared__ float lb[OUTC];
    const int t = threadIdx.x;
    for (int i = t; i < HC * OUTC / 4; i += 256)
        ((float4*)ws)[i] = ((const float4*)lin_W)[i];
    if (t < HC)   bs[t] = bias[t];
    if (t < OUTC) lb[t] = lin_b[t];
    __syncthreads();

    const int warp = t >> 5, lane = t & 31;
    const int hd = lane >> 3;
    const unsigned FULL = 0xffffffffu;

    for (int w = blockIdx.x * 8 + warp; w < NN; w += AGG_BLKS * 8) {
        int beg = g_off[w];
        int end = g_off[w + 1];
        float adh = g_adst[(size_t)w * 4 + hd];

        float4 acc = make_float4(0.f, 0.f, 0.f, 0.f);
        float den = 0.f;

        for (int p = beg; p < end; p += 32) {
            int cnt = end - p; if (cnt > 32) cnt = 32;
            int src = (lane < cnt) ? g_csr[p + lane] : 0;
#pragma unroll 4
            for (int j = 0; j < cnt; j++) {
                int s = __shfl_sync(FULL, src, j);
                float e  = leaky(g_asrc[(size_t)s * 4 + hd] + adh);
                float ex = __expf(e);
                uint2 hv = *(const uint2*)&g_hh[(size_t)s * HC + lane * 4];
                float2 f0 = __half22float2(*(__half2*)&hv.x);
                float2 f1 = __half22float2(*(__half2*)&hv.y);
                acc.x += ex * f0.x;
                acc.y += ex * f0.y;
                acc.z += ex * f1.x;
                acc.w += ex * f1.y;
                den += ex;
            }
        }
        float inv = 1.0f / den;
        float4 bv = *(const float4*)&bs[lane * 4];
        float v0 = acc.x * inv + bv.x; v0 = v0 > 0.f ? v0 : expm1f(v0);
        float v1 = acc.y * inv + bv.y; v1 = v1 > 0.f ? v1 : expm1f(v1);
        float v2 = acc.z * inv + bv.z; v2 = v2 > 0.f ? v2 : expm1f(v2);
        float v3 = acc.w * inv + bv.w; v3 = v3 > 0.f ? v3 : expm1f(v3);
        *(float4*)&stg[warp][lane * 4] = make_float4(v0, v1, v2, v3);
        __syncwarp();

        float acc0 = 0.f, acc1 = 0.f;
#pragma unroll
        for (int kb = 0; kb < 4; kb++) {
            float v = stg[warp][kb * 32 + lane];
#pragma unroll
            for (int j = 0; j < 32; j++) {
                float a = __shfl_sync(FULL, v, j);
                int kk = kb * 32 + j;
                acc0 += a * ws[kk * OUTC + lane];
                acc1 += a * ws[kk * OUTC + 32 + lane];
            }
        }
        out[(size_t)w * OUTC + lane]      = acc0 + lb[lane];
        out[(size_t)w * OUTC + 32 + lane] = acc1 + lb[lane + 32];
        __syncwarp();
    }
}

// ---------------- launch ------------------------------------------------------
extern "C" void kernel_launch(void* const* d_in, const int* in_sizes, int n_in,
                              void* d_out, int out_size) {
    const float* x       = (const float*)d_in[0];
    const int*   eidx    = (const int*)d_in[1];
    const float* W       = (const float*)d_in[2];
    const float* att_src = (const float*)d_in[3];
    const float* att_dst = (const float*)d_in[4];
    const float* bias    = (const float*)d_in[5];
    const float* lin_W   = (const float*)d_in[6];
    const float* lin_b   = (const float*)d_in[7];
    float*       out     = (float*)d_out;

    k_initdeg<<<(NN + 255) / 256, 256>>>();                    // 0
    k_hist   <<<(EE + 255) / 256, 256>>>(eidx);                // 1
    k_cvt    <<<(NN * INC / 8 + 255) / 256, 256>>>(x, W);      // 2
    k_gemm1t <<<(NN + 127) / 128, 256>>>(att_src, att_dst);    // 3  <- profiled
    k_scanA  <<<SCAN_BLKS, 256>>>();                           // 4
    k_scanB  <<<1, 256>>>();                                   // 5
    k_prep   <<<(NN + 255) / 256, 256>>>();                    // 6
    k_scatter<<<(EE + 255) / 256, 256>>>(eidx);                // 7
    k_aggrout<<<AGG_BLKS, 256>>>(bias, lin_W, lin_b, out);     // 8
}

// round 12
// speedup vs baseline: 1.7319x; 1.7319x over previous
#include <cuda_runtime.h>
#include <cuda_fp16.h>
#include <mma.h>
#include <math.h>

using namespace nvcuda;

#define NN   50000
#define EE   1600000
#define ET   (EE + NN)
#define INC  256
#define HC   128
#define HH   4
#define CC   32
#define OUTC 64
#define SCAN_BLKS ((NN + 255) / 256)   // 196

// ---------------- scratch (device globals) ------------------------------------
__device__ __align__(16) __half g_xh[(size_t)NN * INC];     // 25.6 MB fp16 x
__device__ __align__(16) __half g_wh[(size_t)INC * HC];     // 64 KB fp16 W
__device__ __align__(16) __half g_hh[(size_t)NN * HC];      // 12.8 MB fp16 h
__device__ __align__(16) float g_asrc[(size_t)NN * HH];
__device__ __align__(16) float g_adst[(size_t)NN * HH];
__device__ __align__(16) float g_agg[(size_t)NN * HC];      // 25.6 MB
__device__            int   g_deg[NN];
__device__            int   g_off[NN + 1];
__device__            int   g_cur[NN];
__device__            int   g_bsum[SCAN_BLKS];
__device__            int   g_csr[ET];                       // 6.6 MB

// ---------------- helpers ----------------------------------------------------
__device__ __forceinline__ float leaky(float v) {
    return v >= 0.0f ? v : 0.2f * v;
}
__device__ __forceinline__ int clampN(int v) {
    return v < 0 ? 0 : (v >= NN ? NN - 1 : v);
}

// ---------------- tiny init ---------------------------------------------------
__global__ void k_initdeg() {
    int i = blockIdx.x * blockDim.x + threadIdx.x;
    if (i < NN) g_deg[i] = 1;
}

__global__ void k_hist(const int* __restrict__ ei) {
    int i = blockIdx.x * blockDim.x + threadIdx.x;
    if (i >= EE) return;
    atomicAdd(&g_deg[clampN(ei[EE + i])], 1);
}

// ---------------- K0: x,W fp32 -> fp16 ----------------------------------------
__global__ void k_cvt(const float* __restrict__ x, const float* __restrict__ W) {
    int i = blockIdx.x * blockDim.x + threadIdx.x;     // one per 8 elems
    if (i < NN * INC / 8) {
        float4 a = *(const float4*)&x[(size_t)i * 8];
        float4 b = *(const float4*)&x[(size_t)i * 8 + 4];
        __half2 h0 = __floats2half2_rn(a.x, a.y);
        __half2 h1 = __floats2half2_rn(a.z, a.w);
        __half2 h2 = __floats2half2_rn(b.x, b.y);
        __half2 h3 = __floats2half2_rn(b.z, b.w);
        uint4 v;
        v.x = *(unsigned*)&h0; v.y = *(unsigned*)&h1;
        v.z = *(unsigned*)&h2; v.w = *(unsigned*)&h3;
        *(uint4*)&g_xh[(size_t)i * 8] = v;
    }
    if (i < INC * HC / 8) {
        float4 a = *(const float4*)&W[(size_t)i * 8];
        float4 b = *(const float4*)&W[(size_t)i * 8 + 4];
        __half2 h0 = __floats2half2_rn(a.x, a.y);
        __half2 h1 = __floats2half2_rn(a.z, a.w);
        __half2 h2 = __floats2half2_rn(b.x, b.y);
        __half2 h3 = __floats2half2_rn(b.z, b.w);
        uint4 v;
        v.x = *(unsigned*)&h0; v.y = *(unsigned*)&h1;
        v.z = *(unsigned*)&h2; v.w = *(unsigned*)&h3;
        *(uint4*)&g_wh[(size_t)i * 8] = v;
    }
}

// ---------------- K1: h = x @ W via WMMA + fused attention --------------------
// 64x128 block tile; 8 warps in 4x2: warp = 16 rows x 64 cols (4 acc frags).
// Padded smem: xs ld=40 halves (80B), wsb ld=136 halves (272B) — conflict-relief.
__global__ void __launch_bounds__(256) k_gemm1t(
        const float* __restrict__ att_src, const float* __restrict__ att_dst) {
    __shared__ __half xs[64][40];           // 5 KB
    __shared__ __half wsb[32][136];         // 8.5 KB
    __shared__ float  stage[8][16][20];     // 10 KB (ldm=20, mult of 4)

    const int t    = threadIdx.x;
    const int warp = t >> 5;
    const int lane = t & 31;
    const int wr   = warp & 3;              // row strip 0..3
    const int wc   = warp >> 2;             // col half 0..1
    const int row0 = blockIdx.x * 64;
    const int wrow = row0 + wr * 16;

    wmma::fragment<wmma::accumulator, 16, 16, 16, float> acc[4];
#pragma unroll
    for (int j = 0; j < 4; j++) wmma::fill_fragment(acc[j], 0.0f);

    for (int kt = 0; kt < 8; kt++) {
        // x tile: 64 rows x 32 halves = 256 uint4; 1 per thread.
        {
            int r  = t >> 2;
            int hp = t & 3;
            int gr = row0 + r; if (gr >= NN) gr = NN - 1;
            *(uint4*)&xs[r][hp * 8] =
                *(const uint4*)&g_xh[(size_t)gr * INC + kt * 32 + hp * 8];
        }
        // W tile: 32 k x 128 halves = 512 uint4; 2 per thread.
#pragma unroll
        for (int u = 0; u < 2; u++) {
            int id = t + u * 256;
            int rr = id >> 4;
            int c8 = id & 15;
            *(uint4*)&wsb[rr][c8 * 8] =
                *(const uint4*)&g_wh[(size_t)(kt * 32 + rr) * HC + c8 * 8];
        }
        __syncthreads();

#pragma unroll
        for (int ks = 0; ks < 2; ks++) {
            wmma::fragment<wmma::matrix_a, 16, 16, 16, __half, wmma::row_major> af;
            wmma::load_matrix_sync(af, &xs[wr * 16][ks * 16], 40);
#pragma unroll
            for (int j = 0; j < 4; j++) {
                wmma::fragment<wmma::matrix_b, 16, 16, 16, __half, wmma::row_major> bf;
                wmma::load_matrix_sync(bf, &wsb[ks * 16][wc * 64 + j * 16], 136);
                wmma::mma_sync(acc[j], af, bf, acc[j]);
            }
        }
        __syncthreads();
    }

    // Epilogue: warp owns 16 rows x 64 cols = heads wc*2, wc*2+1 (disjoint).
    const int lrow = lane >> 1;
    const int lhp  = lane & 1;
    const int grow = wrow + lrow;
    float sS[2] = {0.f, 0.f};
    float sD[2] = {0.f, 0.f};

#pragma unroll
    for (int j = 0; j < 4; j++) {
        wmma::store_matrix_sync(&stage[warp][0][0], acc[j], 20, wmma::mem_row_major);
        __syncwarp();
        int cb = wc * 64 + j * 16 + lhp * 8;   // global col base of this lane's 8
        int hdl = (j >> 1);                     // local head idx
        const float* sp = &stage[warp][lrow][lhp * 8];
        float4 v0 = make_float4(sp[0], sp[1], sp[2], sp[3]);
        float4 v1 = make_float4(sp[4], sp[5], sp[6], sp[7]);
        float4 aS0 = *(const float4*)&att_src[cb];
        float4 aS1 = *(const float4*)&att_src[cb + 4];
        float4 aD0 = *(const float4*)&att_dst[cb];
        float4 aD1 = *(const float4*)&att_dst[cb + 4];
        sS[hdl] += v0.x * aS0.x + v0.y * aS0.y + v0.z * aS0.z + v0.w * aS0.w
                 + v1.x * aS1.x + v1.y * aS1.y + v1.z * aS1.z + v1.w * aS1.w;
        sD[hdl] += v0.x * aD0.x + v0.y * aD0.y + v0.z * aD0.z + v0.w * aD0.w
                 + v1.x * aD1.x + v1.y * aD1.y + v1.z * aD1.z + v1.w * aD1.w;
        if (grow < NN) {
            __half2 p0 = __floats2half2_rn(v0.x, v0.y);
            __half2 p1 = __floats2half2_rn(v0.z, v0.w);
            __half2 p2 = __floats2half2_rn(v1.x, v1.y);
            __half2 p3 = __floats2half2_rn(v1.z, v1.w);
            uint4 pv;
            pv.x = *(unsigned*)&p0; pv.y = *(unsigned*)&p1;
            pv.z = *(unsigned*)&p2; pv.w = *(unsigned*)&p3;
            *(uint4*)&g_hh[(size_t)grow * HC + cb] = pv;
        }
        __syncwarp();
    }
    // combine the two col-half lanes of each row, write this warp's 2 heads
    const unsigned FULL = 0xffffffffu;
#pragma unroll
    for (int hdl = 0; hdl < 2; hdl++) {
        sS[hdl] += __shfl_xor_sync(FULL, sS[hdl], 1);
        sD[hdl] += __shfl_xor_sync(FULL, sD[hdl], 1);
    }
    if (lhp == 0 && grow < NN) {
        *(float2*)&g_asrc[(size_t)grow * 4 + wc * 2] = make_float2(sS[0], sS[1]);
        *(float2*)&g_adst[(size_t)grow * 4 + wc * 2] = make_float2(sD[0], sD[1]);
    }
}

// ---------------- CSR scan / prep / scatter -----------------------------------
__global__ void k_scanA() {
    __shared__ int sh[256];
    int t = threadIdx.x;
    int idx = blockIdx.x * 256 + t;
    int v = (idx < NN) ? g_deg[idx] : 0;
    sh[t] = v;
    __syncthreads();
#pragma unroll
    for (int o = 1; o < 256; o <<= 1) {
        int u = (t >= o) ? sh[t - o] : 0;
        __syncthreads();
        sh[t] += u;
        __syncthreads();
    }
    if (idx < NN) g_off[idx] = sh[t] - v;
    if (t == 255) g_bsum[blockIdx.x] = sh[255];
}

__global__ void k_scanB() {
    __shared__ int sh[SCAN_BLKS];
    int t = threadIdx.x;
    int v = (t < SCAN_BLKS) ? g_bsum[t] : 0;
    if (t < SCAN_BLKS) sh[t] = v;
    __syncthreads();
    for (int o = 1; o < SCAN_BLKS; o <<= 1) {
        int u = (t >= o && t < SCAN_BLKS) ? sh[t - o] : 0;
        __syncthreads();
        if (t < SCAN_BLKS) sh[t] += u;
        __syncthreads();
    }
    if (t < SCAN_BLKS) g_bsum[t] = sh[t] - v;
}

__global__ void k_prep() {
    int n = blockIdx.x * blockDim.x + threadIdx.x;
    if (n >= NN) return;
    int off = g_off[n] + g_bsum[n >> 8];
    g_off[n] = off;
    g_csr[off] = n;          // self loop first
    g_cur[n] = off + 1;
    if (n == 0) g_off[NN] = ET;
}

__global__ void k_scatter(const int* __restrict__ ei) {
    int i = blockIdx.x * blockDim.x + threadIdx.x;
    if (i >= EE) return;
    int s = clampN(ei[i]);
    int d = clampN(ei[EE + i]);
    int pos = atomicAdd(&g_cur[d], 1);
    g_csr[pos] = s;
}

// ---------------- K6: fused softmax + aggregation (warp per dst, fp16 gather) --
__global__ void k_aggr() {
    int w = (int)((blockIdx.x * (size_t)blockDim.x + threadIdx.x) >> 5);
    if (w >= NN) return;
    int lane = threadIdx.x & 31;
    int hd = lane >> 3;

    int beg = g_off[w];
    int end = g_off[w + 1];
    float adh = g_adst[(size_t)w * 4 + hd];

    float4 acc = make_float4(0.f, 0.f, 0.f, 0.f);
    float den = 0.f;

    for (int p = beg; p < end; p += 32) {
        int cnt = end - p; if (cnt > 32) cnt = 32;
        int src = (lane < cnt) ? g_csr[p + lane] : 0;
#pragma unroll 4
        for (int j = 0; j < cnt; j++) {
            int s = __shfl_sync(0xffffffffu, src, j);
            float e  = leaky(g_asrc[(size_t)s * 4 + hd] + adh);
            float ex = __expf(e);
            uint2 hv = *(const uint2*)&g_hh[(size_t)s * HC + lane * 4];
            float2 f0 = __half22float2(*(__half2*)&hv.x);
            float2 f1 = __half22float2(*(__half2*)&hv.y);
            acc.x += ex * f0.x;
            acc.y += ex * f0.y;
            acc.z += ex * f1.x;
            acc.w += ex * f1.y;
            den += ex;
        }
    }
    float inv = 1.0f / den;
    acc.x *= inv; acc.y *= inv; acc.z *= inv; acc.w *= inv;
    *(float4*)&g_agg[(size_t)w * HC + lane * 4] = acc;
}

// ---------------- K7: out = elu(agg + bias) @ lin_W + lin_b ------------------
__global__ void k_out(const float* __restrict__ bias, const float* __restrict__ lin_W,
                      const float* __restrict__ lin_b, float* __restrict__ out) {
    __shared__ float ws[HC * OUTC];
    __shared__ float bs[HC];
    __shared__ float lb[OUTC];
    int t = threadIdx.x;
    for (int i = t; i < HC * OUTC / 4; i += 256)
        ((float4*)ws)[i] = ((const float4*)lin_W)[i];
    if (t < HC)   bs[t] = bias[t];
    if (t < OUTC) lb[t] = lin_b[t];
    __syncthreads();

    int warp = t >> 5, lane = t & 31;
    for (int r = blockIdx.x * 8 + warp; r < NN; r += gridDim.x * 8) {
        float acc0 = 0.f, acc1 = 0.f;
#pragma unroll
        for (int kb = 0; kb < 4; kb++) {
            int k = kb * 32 + lane;
            float v = g_agg[(size_t)r * HC + k] + bs[k];
            v = v > 0.f ? v : expm1f(v);
#pragma unroll
            for (int j = 0; j < 32; j++) {
                float a = __shfl_sync(0xffffffffu, v, j);
                int kk = kb * 32 + j;
                acc0 += a * ws[kk * OUTC + lane];
                acc1 += a * ws[kk * OUTC + 32 + lane];
            }
        }
        out[(size_t)r * OUTC + lane]      = acc0 + lb[lane];
        out[(size_t)r * OUTC + 32 + lane] = acc1 + lb[lane + 32];
    }
}

// ---------------- launch ------------------------------------------------------
extern "C" void kernel_launch(void* const* d_in, const int* in_sizes, int n_in,
                              void* d_out, int out_size) {
    const float* x       = (const float*)d_in[0];
    const int*   eidx    = (const int*)d_in[1];
    const float* W       = (const float*)d_in[2];
    const float* att_src = (const float*)d_in[3];
    const float* att_dst = (const float*)d_in[4];
    const float* bias    = (const float*)d_in[5];
    const float* lin_b   = (const float*)d_in[7];
    const float* lin_W   = (const float*)d_in[6];
    float*       out     = (float*)d_out;

    k_initdeg<<<(NN + 255) / 256, 256>>>();                    // 0
    k_hist   <<<(EE + 255) / 256, 256>>>(eidx);                // 1
    k_cvt    <<<(NN * INC / 8 + 255) / 256, 256>>>(x, W);      // 2
    k_gemm1t <<<(NN + 63) / 64, 256>>>(att_src, att_dst);      // 3  <- profiled
    k_scanA  <<<SCAN_BLKS, 256>>>();                           // 4
    k_scanB  <<<1, 256>>>();                                   // 5
    k_prep   <<<(NN + 255) / 256, 256>>>();                    // 6
    k_scatter<<<(EE + 255) / 256, 256>>>(eidx);                // 7
    k_aggr   <<<(NN * 32 + 255) / 256, 256>>>();               // 8
    k_out    <<<625, 256>>>(bias, lin_W, lin_b, out);          // 9
}

// round 13
// speedup vs baseline: 2.4682x; 1.4252x over previous
#include <cuda_runtime.h>
#include <cuda_fp16.h>
#include <mma.h>
#include <math.h>

using namespace nvcuda;

#define NN   50000
#define NPAD 50048          // 391 * 128
#define EE   1600000
#define ET   (EE + NN)
#define INC  256
#define HC   128
#define HH   4
#define CC   32
#define OUTC 64
#define SCAN_BLKS ((NN + 255) / 256)   // 196

// ---------------- scratch (device globals) ------------------------------------
__device__ __align__(16) __half g_xh[(size_t)NN * INC];     // 25.6 MB fp16 x
__device__ __align__(16) __half g_wh[(size_t)INC * HC];     // 64 KB fp16 W
__device__ __align__(16) __half g_lwh[(size_t)HC * OUTC];   // 16 KB fp16 lin_W
__device__ __align__(16) __half g_hh[(size_t)NN * HC];      // 12.8 MB fp16 h
__device__ __align__(16) __half g_aggh[(size_t)NPAD * HC];  // 12.8 MB fp16 elu(agg+bias)
__device__ __align__(16) float g_asrc[(size_t)NN * HH];
__device__ __align__(16) float g_adst[(size_t)NN * HH];
__device__            int   g_deg[NN];
__device__            int   g_off[NN + 1];
__device__            int   g_cur[NN];
__device__            int   g_bsum[SCAN_BLKS];
__device__            int   g_csr[ET];                       // 6.6 MB

// ---------------- helpers ----------------------------------------------------
__device__ __forceinline__ float leaky(float v) {
    return v >= 0.0f ? v : 0.2f * v;
}
__device__ __forceinline__ int clampN(int v) {
    return v < 0 ? 0 : (v >= NN ? NN - 1 : v);
}

// ---------------- tiny init ---------------------------------------------------
__global__ void k_initdeg() {
    int i = blockIdx.x * blockDim.x + threadIdx.x;
    if (i < NN) g_deg[i] = 1;
}

// 4 edges per thread (int4)
__global__ void k_hist(const int* __restrict__ ei) {
    int i = blockIdx.x * blockDim.x + threadIdx.x;
    if (i >= EE / 4) return;
    int4 d = *(const int4*)&ei[EE + i * 4];
    atomicAdd(&g_deg[clampN(d.x)], 1);
    atomicAdd(&g_deg[clampN(d.y)], 1);
    atomicAdd(&g_deg[clampN(d.z)], 1);
    atomicAdd(&g_deg[clampN(d.w)], 1);
}

// ---------------- K0: x, W, lin_W fp32 -> fp16 --------------------------------
__global__ void k_cvt(const float* __restrict__ x, const float* __restrict__ W,
                      const float* __restrict__ lin_W) {
    int i = blockIdx.x * blockDim.x + threadIdx.x;     // one per 8 elems
    if (i < NN * INC / 8) {
        float4 a = *(const float4*)&x[(size_t)i * 8];
        float4 b = *(const float4*)&x[(size_t)i * 8 + 4];
        __half2 h0 = __floats2half2_rn(a.x, a.y);
        __half2 h1 = __floats2half2_rn(a.z, a.w);
        __half2 h2 = __floats2half2_rn(b.x, b.y);
        __half2 h3 = __floats2half2_rn(b.z, b.w);
        uint4 v;
        v.x = *(unsigned*)&h0; v.y = *(unsigned*)&h1;
        v.z = *(unsigned*)&h2; v.w = *(unsigned*)&h3;
        *(uint4*)&g_xh[(size_t)i * 8] = v;
    }
    if (i < INC * HC / 8) {
        float4 a = *(const float4*)&W[(size_t)i * 8];
        float4 b = *(const float4*)&W[(size_t)i * 8 + 4];
        __half2 h0 = __floats2half2_rn(a.x, a.y);
        __half2 h1 = __floats2half2_rn(a.z, a.w);
        __half2 h2 = __floats2half2_rn(b.x, b.y);
        __half2 h3 = __floats2half2_rn(b.z, b.w);
        uint4 v;
        v.x = *(unsigned*)&h0; v.y = *(unsigned*)&h1;
        v.z = *(unsigned*)&h2; v.w = *(unsigned*)&h3;
        *(uint4*)&g_wh[(size_t)i * 8] = v;
    }
    if (i < HC * OUTC / 8) {
        float4 a = *(const float4*)&lin_W[(size_t)i * 8];
        float4 b = *(const float4*)&lin_W[(size_t)i * 8 + 4];
        __half2 h0 = __floats2half2_rn(a.x, a.y);
        __half2 h1 = __floats2half2_rn(a.z, a.w);
        __half2 h2 = __floats2half2_rn(b.x, b.y);
        __half2 h3 = __floats2half2_rn(b.z, b.w);
        uint4 v;
        v.x = *(unsigned*)&h0; v.y = *(unsigned*)&h1;
        v.z = *(unsigned*)&h2; v.w = *(unsigned*)&h3;
        *(uint4*)&g_lwh[(size_t)i * 8] = v;
    }
}

// ---------------- K1: h = x @ W via WMMA + fused attention --------------------
__global__ void __launch_bounds__(256) k_gemm1t(
        const float* __restrict__ att_src, const float* __restrict__ att_dst) {
    __shared__ __half xs[64][40];           // 5 KB
    __shared__ __half wsb[32][136];         // 8.5 KB
    __shared__ float  stage[8][16][20];     // 10 KB

    const int t    = threadIdx.x;
    const int warp = t >> 5;
    const int lane = t & 31;
    const int wr   = warp & 3;
    const int wc   = warp >> 2;
    const int row0 = blockIdx.x * 64;
    const int wrow = row0 + wr * 16;

    wmma::fragment<wmma::accumulator, 16, 16, 16, float> acc[4];
#pragma unroll
    for (int j = 0; j < 4; j++) wmma::fill_fragment(acc[j], 0.0f);

    for (int kt = 0; kt < 8; kt++) {
        {
            int r  = t >> 2;
            int hp = t & 3;
            int gr = row0 + r; if (gr >= NN) gr = NN - 1;
            *(uint4*)&xs[r][hp * 8] =
                *(const uint4*)&g_xh[(size_t)gr * INC + kt * 32 + hp * 8];
        }
#pragma unroll
        for (int u = 0; u < 2; u++) {
            int id = t + u * 256;
            int rr = id >> 4;
            int c8 = id & 15;
            *(uint4*)&wsb[rr][c8 * 8] =
                *(const uint4*)&g_wh[(size_t)(kt * 32 + rr) * HC + c8 * 8];
        }
        __syncthreads();

#pragma unroll
        for (int ks = 0; ks < 2; ks++) {
            wmma::fragment<wmma::matrix_a, 16, 16, 16, __half, wmma::row_major> af;
            wmma::load_matrix_sync(af, &xs[wr * 16][ks * 16], 40);
#pragma unroll
            for (int j = 0; j < 4; j++) {
                wmma::fragment<wmma::matrix_b, 16, 16, 16, __half, wmma::row_major> bf;
                wmma::load_matrix_sync(bf, &wsb[ks * 16][wc * 64 + j * 16], 136);
                wmma::mma_sync(acc[j], af, bf, acc[j]);
            }
        }
        __syncthreads();
    }

    const int lrow = lane >> 1;
    const int lhp  = lane & 1;
    const int grow = wrow + lrow;
    float sS[2] = {0.f, 0.f};
    float sD[2] = {0.f, 0.f};

#pragma unroll
    for (int j = 0; j < 4; j++) {
        wmma::store_matrix_sync(&stage[warp][0][0], acc[j], 20, wmma::mem_row_major);
        __syncwarp();
        int cb = wc * 64 + j * 16 + lhp * 8;
        int hdl = (j >> 1);
        const float* sp = &stage[warp][lrow][lhp * 8];
        float4 v0 = make_float4(sp[0], sp[1], sp[2], sp[3]);
        float4 v1 = make_float4(sp[4], sp[5], sp[6], sp[7]);
        float4 aS0 = *(const float4*)&att_src[cb];
        float4 aS1 = *(const float4*)&att_src[cb + 4];
        float4 aD0 = *(const float4*)&att_dst[cb];
        float4 aD1 = *(const float4*)&att_dst[cb + 4];
        sS[hdl] += v0.x * aS0.x + v0.y * aS0.y + v0.z * aS0.z + v0.w * aS0.w
                 + v1.x * aS1.x + v1.y * aS1.y + v1.z * aS1.z + v1.w * aS1.w;
        sD[hdl] += v0.x * aD0.x + v0.y * aD0.y + v0.z * aD0.z + v0.w * aD0.w
                 + v1.x * aD1.x + v1.y * aD1.y + v1.z * aD1.z + v1.w * aD1.w;
        if (grow < NN) {
            __half2 p0 = __floats2half2_rn(v0.x, v0.y);
            __half2 p1 = __floats2half2_rn(v0.z, v0.w);
            __half2 p2 = __floats2half2_rn(v1.x, v1.y);
            __half2 p3 = __floats2half2_rn(v1.z, v1.w);
            uint4 pv;
            pv.x = *(unsigned*)&p0; pv.y = *(unsigned*)&p1;
            pv.z = *(unsigned*)&p2; pv.w = *(unsigned*)&p3;
            *(uint4*)&g_hh[(size_t)grow * HC + cb] = pv;
        }
        __syncwarp();
    }
    const unsigned FULL = 0xffffffffu;
#pragma unroll
    for (int hdl = 0; hdl < 2; hdl++) {
        sS[hdl] += __shfl_xor_sync(FULL, sS[hdl], 1);
        sD[hdl] += __shfl_xor_sync(FULL, sD[hdl], 1);
    }
    if (lhp == 0 && grow < NN) {
        *(float2*)&g_asrc[(size_t)grow * 4 + wc * 2] = make_float2(sS[0], sS[1]);
        *(float2*)&g_adst[(size_t)grow * 4 + wc * 2] = make_float2(sD[0], sD[1]);
    }
}

// ---------------- CSR scan / prep / scatter -----------------------------------
__global__ void k_scanA() {
    __shared__ int sh[256];
    int t = threadIdx.x;
    int idx = blockIdx.x * 256 + t;
    int v = (idx < NN) ? g_deg[idx] : 0;
    sh[t] = v;
    __syncthreads();
#pragma unroll
    for (int o = 1; o < 256; o <<= 1) {
        int u = (t >= o) ? sh[t - o] : 0;
        __syncthreads();
        sh[t] += u;
        __syncthreads();
    }
    if (idx < NN) g_off[idx] = sh[t] - v;
    if (t == 255) g_bsum[blockIdx.x] = sh[255];
}

__global__ void k_scanB() {
    __shared__ int sh[SCAN_BLKS];
    int t = threadIdx.x;
    int v = (t < SCAN_BLKS) ? g_bsum[t] : 0;
    if (t < SCAN_BLKS) sh[t] = v;
    __syncthreads();
    for (int o = 1; o < SCAN_BLKS; o <<= 1) {
        int u = (t >= o && t < SCAN_BLKS) ? sh[t - o] : 0;
        __syncthreads();
        if (t < SCAN_BLKS) sh[t] += u;
        __syncthreads();
    }
    if (t < SCAN_BLKS) g_bsum[t] = sh[t] - v;
}

__global__ void k_prep() {
    int n = blockIdx.x * blockDim.x + threadIdx.x;
    if (n >= NN) return;
    int off = g_off[n] + g_bsum[n >> 8];
    g_off[n] = off;
    g_csr[off] = n;          // self loop first
    g_cur[n] = off + 1;
    if (n == 0) g_off[NN] = ET;
}

// 4 edges per thread (int4)
__global__ void k_scatter(const int* __restrict__ ei) {
    int i = blockIdx.x * blockDim.x + threadIdx.x;
    if (i >= EE / 4) return;
    int4 s = *(const int4*)&ei[i * 4];
    int4 d = *(const int4*)&ei[EE + i * 4];
    g_csr[atomicAdd(&g_cur[clampN(d.x)], 1)] = clampN(s.x);
    g_csr[atomicAdd(&g_cur[clampN(d.y)], 1)] = clampN(s.y);
    g_csr[atomicAdd(&g_cur[clampN(d.z)], 1)] = clampN(s.z);
    g_csr[atomicAdd(&g_cur[clampN(d.w)], 1)] = clampN(s.w);
}

// ---------------- K6: softmax + aggregation + bias + ELU (fp16 out) -----------
__global__ void k_aggr(const float* __restrict__ bias) {
    int w = (int)((blockIdx.x * (size_t)blockDim.x + threadIdx.x) >> 5);
    if (w >= NN) return;
    int lane = threadIdx.x & 31;
    int hd = lane >> 3;

    int beg = g_off[w];
    int end = g_off[w + 1];
    float adh = g_adst[(size_t)w * 4 + hd];
    float4 bv = *(const float4*)&bias[lane * 4];

    float4 acc = make_float4(0.f, 0.f, 0.f, 0.f);
    float den = 0.f;

    for (int p = beg; p < end; p += 32) {
        int cnt = end - p; if (cnt > 32) cnt = 32;
        int src = (lane < cnt) ? g_csr[p + lane] : 0;
#pragma unroll 4
        for (int j = 0; j < cnt; j++) {
            int s = __shfl_sync(0xffffffffu, src, j);
            float e  = leaky(g_asrc[(size_t)s * 4 + hd] + adh);
            float ex = __expf(e);
            uint2 hv = *(const uint2*)&g_hh[(size_t)s * HC + lane * 4];
            float2 f0 = __half22float2(*(__half2*)&hv.x);
            float2 f1 = __half22float2(*(__half2*)&hv.y);
            acc.x += ex * f0.x;
            acc.y += ex * f0.y;
            acc.z += ex * f1.x;
            acc.w += ex * f1.y;
            den += ex;
        }
    }
    float inv = 1.0f / den;
    float v0 = acc.x * inv + bv.x; v0 = v0 > 0.f ? v0 : expm1f(v0);
    float v1 = acc.y * inv + bv.y; v1 = v1 > 0.f ? v1 : expm1f(v1);
    float v2 = acc.z * inv + bv.z; v2 = v2 > 0.f ? v2 : expm1f(v2);
    float v3 = acc.w * inv + bv.w; v3 = v3 > 0.f ? v3 : expm1f(v3);
    __half2 h0 = __floats2half2_rn(v0, v1);
    __half2 h1 = __floats2half2_rn(v2, v3);
    uint2 st;
    st.x = *(unsigned*)&h0; st.y = *(unsigned*)&h1;
    *(uint2*)&g_aggh[(size_t)w * HC + lane * 4] = st;
}

// ---------------- K7: out = aggh @ lin_Wh + lin_b via WMMA --------------------
// 391 blocks x 128 rows; 8 warps, 16 rows each. A from global (ld=128), B smem.
__global__ void __launch_bounds__(256) k_out2(
        const float* __restrict__ lin_b, float* __restrict__ out) {
    __shared__ __half lw[HC][72];           // 18.4 KB (padded)
    __shared__ float  stage[8][16][20];     // 10 KB
    __shared__ float  lb[OUTC];

    const int t    = threadIdx.x;
    const int warp = t >> 5;
    const int lane = t & 31;
    const int row0 = blockIdx.x * 128 + warp * 16;

    // load lin_W fp16: 128x64 = 1024 uint4; 4 per thread
#pragma unroll
    for (int u = 0; u < 4; u++) {
        int id = t + u * 256;
        int r  = id >> 3;
        int c8 = id & 7;
        *(uint4*)&lw[r][c8 * 8] = *(const uint4*)&g_lwh[(size_t)r * OUTC + c8 * 8];
    }
    if (t < OUTC) lb[t] = lin_b[t];
    __syncthreads();

    wmma::fragment<wmma::accumulator, 16, 16, 16, float> acc[4];
#pragma unroll
    for (int j = 0; j < 4; j++) wmma::fill_fragment(acc[j], 0.0f);

#pragma unroll
    for (int k = 0; k < 8; k++) {
        wmma::fragment<wmma::matrix_a, 16, 16, 16, __half, wmma::row_major> af;
        wmma::load_matrix_sync(af, &g_aggh[(size_t)row0 * HC + k * 16], HC);
#pragma unroll
        for (int j = 0; j < 4; j++) {
            wmma::fragment<wmma::matrix_b, 16, 16, 16, __half, wmma::row_major> bf;
            wmma::load_matrix_sync(bf, &lw[k * 16][j * 16], 72);
            wmma::mma_sync(acc[j], af, bf, acc[j]);
        }
    }

    const int lrow = lane >> 1;
    const int lhp  = lane & 1;
    const int grow = row0 + lrow;
#pragma unroll
    for (int j = 0; j < 4; j++) {
        wmma::store_matrix_sync(&stage[warp][0][0], acc[j], 20, wmma::mem_row_major);
        __syncwarp();
        if (grow < NN) {
            int cb = j * 16 + lhp * 8;
            const float* sp = &stage[warp][lrow][lhp * 8];
            float4 o0 = make_float4(sp[0] + lb[cb],     sp[1] + lb[cb + 1],
                                    sp[2] + lb[cb + 2], sp[3] + lb[cb + 3]);
            float4 o1 = make_float4(sp[4] + lb[cb + 4], sp[5] + lb[cb + 5],
                                    sp[6] + lb[cb + 6], sp[7] + lb[cb + 7]);
            *(float4*)&out[(size_t)grow * OUTC + cb]     = o0;
            *(float4*)&out[(size_t)grow * OUTC + cb + 4] = o1;
        }
        __syncwarp();
    }
}

// ---------------- launch ------------------------------------------------------
extern "C" void kernel_launch(void* const* d_in, const int* in_sizes, int n_in,
                              void* d_out, int out_size) {
    const float* x       = (const float*)d_in[0];
    const int*   eidx    = (const int*)d_in[1];
    const float* W       = (const float*)d_in[2];
    const float* att_src = (const float*)d_in[3];
    const float* att_dst = (const float*)d_in[4];
    const float* bias    = (const float*)d_in[5];
    const float* lin_W   = (const float*)d_in[6];
    const float* lin_b   = (const float*)d_in[7];
    float*       out     = (float*)d_out;

    k_initdeg<<<(NN + 255) / 256, 256>>>();                        // 0
    k_hist   <<<(EE / 4 + 255) / 256, 256>>>(eidx);                // 1
    k_cvt    <<<(NN * INC / 8 + 255) / 256, 256>>>(x, W, lin_W);   // 2
    k_gemm1t <<<(NN + 63) / 64, 256>>>(att_src, att_dst);          // 3  <- profiled
    k_scanA  <<<SCAN_BLKS, 256>>>();                               // 4
    k_scanB  <<<1, 256>>>();                                       // 5
    k_prep   <<<(NN + 255) / 256, 256>>>();                        // 6
    k_scatter<<<(EE / 4 + 255) / 256, 256>>>(eidx);                // 7
    k_aggr   <<<(NN * 32 + 255) / 256, 256>>>(bias);               // 8
    k_out2   <<<(NPAD / 128), 256>>>(lin_b, out);                  // 9
}

// round 14
// speedup vs baseline: 2.6286x; 1.0650x over previous
#include <cuda_runtime.h>
#include <cuda_fp16.h>
#include <mma.h>
#include <math.h>

using namespace nvcuda;

#define NN   50000
#define NPAD 50048          // 391 * 128
#define EE   1600000
#define ET   (EE + NN)
#define INC  256
#define HC   128
#define HH   4
#define CC   32
#define OUTC 64
#define SCAN_BLKS ((NN + 255) / 256)   // 196

// ---------------- scratch (device globals) ------------------------------------
__device__ __align__(16) __half g_xh[(size_t)NN * INC];     // 25.6 MB fp16 x
__device__ __align__(16) __half g_wh[(size_t)INC * HC];     // 64 KB fp16 W
__device__ __align__(16) __half g_lwh[(size_t)HC * OUTC];   // 16 KB fp16 lin_W
__device__ __align__(16) __half g_hh[(size_t)NN * HC];      // 12.8 MB fp16 h
__device__ __align__(16) __half g_aggh[(size_t)NPAD * HC];  // 12.8 MB fp16 elu(agg+bias)
__device__ __align__(16) float g_asrc[(size_t)NN * HH];
__device__ __align__(16) float g_adst[(size_t)NN * HH];
__device__            int   g_deg[NN];
__device__            int   g_off[NN + 1];
__device__            int   g_cur[NN];
__device__            int   g_bsum[SCAN_BLKS];
__device__            int   g_csr[ET];                       // 6.6 MB

// ---------------- helpers ----------------------------------------------------
__device__ __forceinline__ float leaky(float v) {
    return v >= 0.0f ? v : 0.2f * v;
}
__device__ __forceinline__ int clampN(int v) {
    return v < 0 ? 0 : (v >= NN ? NN - 1 : v);
}

// ---------------- K0: x, W, lin_W fp32 -> fp16 (+ deg init) -------------------
__global__ void k_cvt(const float* __restrict__ x, const float* __restrict__ W,
                      const float* __restrict__ lin_W) {
    int i = blockIdx.x * blockDim.x + threadIdx.x;     // one per 8 elems
    if (i < NN * INC / 8) {
        float4 a = *(const float4*)&x[(size_t)i * 8];
        float4 b = *(const float4*)&x[(size_t)i * 8 + 4];
        __half2 h0 = __floats2half2_rn(a.x, a.y);
        __half2 h1 = __floats2half2_rn(a.z, a.w);
        __half2 h2 = __floats2half2_rn(b.x, b.y);
        __half2 h3 = __floats2half2_rn(b.z, b.w);
        uint4 v;
        v.x = *(unsigned*)&h0; v.y = *(unsigned*)&h1;
        v.z = *(unsigned*)&h2; v.w = *(unsigned*)&h3;
        *(uint4*)&g_xh[(size_t)i * 8] = v;
    }
    if (i < INC * HC / 8) {
        float4 a = *(const float4*)&W[(size_t)i * 8];
        float4 b = *(const float4*)&W[(size_t)i * 8 + 4];
        __half2 h0 = __floats2half2_rn(a.x, a.y);
        __half2 h1 = __floats2half2_rn(a.z, a.w);
        __half2 h2 = __floats2half2_rn(b.x, b.y);
        __half2 h3 = __floats2half2_rn(b.z, b.w);
        uint4 v;
        v.x = *(unsigned*)&h0; v.y = *(unsigned*)&h1;
        v.z = *(unsigned*)&h2; v.w = *(unsigned*)&h3;
        *(uint4*)&g_wh[(size_t)i * 8] = v;
    }
    if (i < HC * OUTC / 8) {
        float4 a = *(const float4*)&lin_W[(size_t)i * 8];
        float4 b = *(const float4*)&lin_W[(size_t)i * 8 + 4];
        __half2 h0 = __floats2half2_rn(a.x, a.y);
        __half2 h1 = __floats2half2_rn(a.z, a.w);
        __half2 h2 = __floats2half2_rn(b.x, b.y);
        __half2 h3 = __floats2half2_rn(b.z, b.w);
        uint4 v;
        v.x = *(unsigned*)&h0; v.y = *(unsigned*)&h1;
        v.z = *(unsigned*)&h2; v.w = *(unsigned*)&h3;
        *(uint4*)&g_lwh[(size_t)i * 8] = v;
    }
    if (i < NN) g_deg[i] = 1;     // self loop
}

// ---------------- histogram of destinations (4 edges/thread) ------------------
__global__ void k_hist(const int* __restrict__ ei) {
    int i = blockIdx.x * blockDim.x + threadIdx.x;
    if (i >= EE / 4) return;
    int4 d = *(const int4*)&ei[EE + i * 4];
    atomicAdd(&g_deg[clampN(d.x)], 1);
    atomicAdd(&g_deg[clampN(d.y)], 1);
    atomicAdd(&g_deg[clampN(d.z)], 1);
    atomicAdd(&g_deg[clampN(d.w)], 1);
}

// ---------------- K1: h = x @ W via WMMA + fused attention --------------------
__global__ void __launch_bounds__(256) k_gemm1t(
        const float* __restrict__ att_src, const float* __restrict__ att_dst) {
    __shared__ __half xs[64][40];           // 5 KB
    __shared__ __half wsb[32][136];         // 8.5 KB
    __shared__ float  stage[8][16][20];     // 10 KB

    const int t    = threadIdx.x;
    const int warp = t >> 5;
    const int lane = t & 31;
    const int wr   = warp & 3;
    const int wc   = warp >> 2;
    const int row0 = blockIdx.x * 64;
    const int wrow = row0 + wr * 16;

    wmma::fragment<wmma::accumulator, 16, 16, 16, float> acc[4];
#pragma unroll
    for (int j = 0; j < 4; j++) wmma::fill_fragment(acc[j], 0.0f);

    for (int kt = 0; kt < 8; kt++) {
        {
            int r  = t >> 2;
            int hp = t & 3;
            int gr = row0 + r; if (gr >= NN) gr = NN - 1;
            *(uint4*)&xs[r][hp * 8] =
                *(const uint4*)&g_xh[(size_t)gr * INC + kt * 32 + hp * 8];
        }
#pragma unroll
        for (int u = 0; u < 2; u++) {
            int id = t + u * 256;
            int rr = id >> 4;
            int c8 = id & 15;
            *(uint4*)&wsb[rr][c8 * 8] =
                *(const uint4*)&g_wh[(size_t)(kt * 32 + rr) * HC + c8 * 8];
        }
        __syncthreads();

#pragma unroll
        for (int ks = 0; ks < 2; ks++) {
            wmma::fragment<wmma::matrix_a, 16, 16, 16, __half, wmma::row_major> af;
            wmma::load_matrix_sync(af, &xs[wr * 16][ks * 16], 40);
#pragma unroll
            for (int j = 0; j < 4; j++) {
                wmma::fragment<wmma::matrix_b, 16, 16, 16, __half, wmma::row_major> bf;
                wmma::load_matrix_sync(bf, &wsb[ks * 16][wc * 64 + j * 16], 136);
                wmma::mma_sync(acc[j], af, bf, acc[j]);
            }
        }
        __syncthreads();
    }

    const int lrow = lane >> 1;
    const int lhp  = lane & 1;
    const int grow = wrow + lrow;
    float sS[2] = {0.f, 0.f};
    float sD[2] = {0.f, 0.f};

#pragma unroll
    for (int j = 0; j < 4; j++) {
        wmma::store_matrix_sync(&stage[warp][0][0], acc[j], 20, wmma::mem_row_major);
        __syncwarp();
        int cb = wc * 64 + j * 16 + lhp * 8;
        int hdl = (j >> 1);
        const float* sp = &stage[warp][lrow][lhp * 8];
        float4 v0 = make_float4(sp[0], sp[1], sp[2], sp[3]);
        float4 v1 = make_float4(sp[4], sp[5], sp[6], sp[7]);
        float4 aS0 = *(const float4*)&att_src[cb];
        float4 aS1 = *(const float4*)&att_src[cb + 4];
        float4 aD0 = *(const float4*)&att_dst[cb];
        float4 aD1 = *(const float4*)&att_dst[cb + 4];
        sS[hdl] += v0.x * aS0.x + v0.y * aS0.y + v0.z * aS0.z + v0.w * aS0.w
                 + v1.x * aS1.x + v1.y * aS1.y + v1.z * aS1.z + v1.w * aS1.w;
        sD[hdl] += v0.x * aD0.x + v0.y * aD0.y + v0.z * aD0.z + v0.w * aD0.w
                 + v1.x * aD1.x + v1.y * aD1.y + v1.z * aD1.z + v1.w * aD1.w;
        if (grow < NN) {
            __half2 p0 = __floats2half2_rn(v0.x, v0.y);
            __half2 p1 = __floats2half2_rn(v0.z, v0.w);
            __half2 p2 = __floats2half2_rn(v1.x, v1.y);
            __half2 p3 = __floats2half2_rn(v1.z, v1.w);
            uint4 pv;
            pv.x = *(unsigned*)&p0; pv.y = *(unsigned*)&p1;
            pv.z = *(unsigned*)&p2; pv.w = *(unsigned*)&p3;
            *(uint4*)&g_hh[(size_t)grow * HC + cb] = pv;
        }
        __syncwarp();
    }
    const unsigned FULL = 0xffffffffu;
#pragma unroll
    for (int hdl = 0; hdl < 2; hdl++) {
        sS[hdl] += __shfl_xor_sync(FULL, sS[hdl], 1);
        sD[hdl] += __shfl_xor_sync(FULL, sD[hdl], 1);
    }
    if (lhp == 0 && grow < NN) {
        *(float2*)&g_asrc[(size_t)grow * 4 + wc * 2] = make_float2(sS[0], sS[1]);
        *(float2*)&g_adst[(size_t)grow * 4 + wc * 2] = make_float2(sD[0], sD[1]);
    }
}

// ---------------- CSR: scanA, then prep (with inlined bsum prefix) ------------
__global__ void k_scanA() {
    __shared__ int sh[256];
    int t = threadIdx.x;
    int idx = blockIdx.x * 256 + t;
    int v = (idx < NN) ? g_deg[idx] : 0;
    sh[t] = v;
    __syncthreads();
#pragma unroll
    for (int o = 1; o < 256; o <<= 1) {
        int u = (t >= o) ? sh[t - o] : 0;
        __syncthreads();
        sh[t] += u;
        __syncthreads();
    }
    if (idx < NN) g_off[idx] = sh[t] - v;
    if (t == 255) g_bsum[blockIdx.x] = sh[255];
}

// block b: base = sum(bsum[0..b)), then finalize its 256 nodes
__global__ void k_prep() {
    __shared__ int red[256];
    int b = blockIdx.x;
    int t = threadIdx.x;
    int v = (t < b && t < SCAN_BLKS) ? g_bsum[t] : 0;
    red[t] = v;
    __syncthreads();
#pragma unroll
    for (int o = 128; o > 0; o >>= 1) {
        if (t < o) red[t] += red[t + o];
        __syncthreads();
    }
    int base = red[0];
    int n = b * 256 + t;
    if (n < NN) {
        int off = g_off[n] + base;
        g_off[n] = off;
        g_csr[off] = n;          // self loop first
        g_cur[n] = off + 1;
        if (n == 0) g_off[NN] = ET;
    }
}

// scatter edges into CSR by destination (4 edges/thread)
__global__ void k_scatter(const int* __restrict__ ei) {
    int i = blockIdx.x * blockDim.x + threadIdx.x;
    if (i >= EE / 4) return;
    int4 s = *(const int4*)&ei[i * 4];
    int4 d = *(const int4*)&ei[EE + i * 4];
    g_csr[atomicAdd(&g_cur[clampN(d.x)], 1)] = clampN(s.x);
    g_csr[atomicAdd(&g_cur[clampN(d.y)], 1)] = clampN(s.y);
    g_csr[atomicAdd(&g_cur[clampN(d.z)], 1)] = clampN(s.z);
    g_csr[atomicAdd(&g_cur[clampN(d.w)], 1)] = clampN(s.w);
}

// ---------------- K6: softmax + aggregation + bias + ELU (2 edges/iter) -------
// warp = 1 dst node; two 16-lane halves each process one edge per iter with
// uint4 (8-half) loads. Cross-half reduction at the end.
__global__ void k_aggr(const float* __restrict__ bias) {
    int w = (int)((blockIdx.x * (size_t)blockDim.x + threadIdx.x) >> 5);
    if (w >= NN) return;
    const int lane = threadIdx.x & 31;
    const int half = lane >> 4;            // 0 or 1
    const int hl   = lane & 15;            // 0..15
    const int cb   = hl * 8;               // channel base (8 channels)
    const int hd   = hl >> 2;              // head of these 8 channels
    const unsigned FULL = 0xffffffffu;

    int beg = g_off[w];
    int end = g_off[w + 1];
    float adh = g_adst[(size_t)w * 4 + hd];

    float acc[8] = {0.f, 0.f, 0.f, 0.f, 0.f, 0.f, 0.f, 0.f};
    float den = 0.f;

    for (int p = beg; p < end; p += 32) {
        int cnt = end - p; if (cnt > 32) cnt = 32;
        int src = (lane < cnt) ? g_csr[p + lane] : 0;
        int iters = (cnt + 1) >> 1;
#pragma unroll 4
        for (int t2 = 0; t2 < iters; t2++) {
            int my_e = t2 * 2 + half;
            int s = __shfl_sync(FULL, src, my_e & 31);
            bool valid = (my_e < cnt);
            float e  = leaky(g_asrc[(size_t)s * 4 + hd] + adh);
            float ex = valid ? __expf(e) : 0.f;
            uint4 hv = *(const uint4*)&g_hh[(size_t)s * HC + cb];
            float2 f0 = __half22float2(*(__half2*)&hv.x);
            float2 f1 = __half22float2(*(__half2*)&hv.y);
            float2 f2 = __half22float2(*(__half2*)&hv.z);
            float2 f3 = __half22float2(*(__half2*)&hv.w);
            acc[0] += ex * f0.x; acc[1] += ex * f0.y;
            acc[2] += ex * f1.x; acc[3] += ex * f1.y;
            acc[4] += ex * f2.x; acc[5] += ex * f2.y;
            acc[6] += ex * f3.x; acc[7] += ex * f3.y;
            den += ex;
        }
    }
    // combine the two halves (channels identical, edges disjoint)
#pragma unroll
    for (int c = 0; c < 8; c++) acc[c] += __shfl_xor_sync(FULL, acc[c], 16);
    den += __shfl_xor_sync(FULL, den, 16);

    if (half == 0) {
        float inv = 1.0f / den;
        float4 b0 = *(const float4*)&bias[cb];
        float4 b1 = *(const float4*)&bias[cb + 4];
        float v0 = acc[0] * inv + b0.x; v0 = v0 > 0.f ? v0 : expm1f(v0);
        float v1 = acc[1] * inv + b0.y; v1 = v1 > 0.f ? v1 : expm1f(v1);
        float v2 = acc[2] * inv + b0.z; v2 = v2 > 0.f ? v2 : expm1f(v2);
        float v3 = acc[3] * inv + b0.w; v3 = v3 > 0.f ? v3 : expm1f(v3);
        float v4 = acc[4] * inv + b1.x; v4 = v4 > 0.f ? v4 : expm1f(v4);
        float v5 = acc[5] * inv + b1.y; v5 = v5 > 0.f ? v5 : expm1f(v5);
        float v6 = acc[6] * inv + b1.z; v6 = v6 > 0.f ? v6 : expm1f(v6);
        float v7 = acc[7] * inv + b1.w; v7 = v7 > 0.f ? v7 : expm1f(v7);
        __half2 h0 = __floats2half2_rn(v0, v1);
        __half2 h1 = __floats2half2_rn(v2, v3);
        __half2 h2 = __floats2half2_rn(v4, v5);
        __half2 h3 = __floats2half2_rn(v6, v7);
        uint4 st;
        st.x = *(unsigned*)&h0; st.y = *(unsigned*)&h1;
        st.z = *(unsigned*)&h2; st.w = *(unsigned*)&h3;
        *(uint4*)&g_aggh[(size_t)w * HC + cb] = st;
    }
}

// ---------------- K7: out = aggh @ lin_Wh + lin_b via WMMA --------------------
__global__ void __launch_bounds__(256) k_out2(
        const float* __restrict__ lin_b, float* __restrict__ out) {
    __shared__ __half lw[HC][72];           // 18.4 KB (padded)
    __shared__ float  stage[8][16][20];     // 10 KB
    __shared__ float  lb[OUTC];

    const int t    = threadIdx.x;
    const int warp = t >> 5;
    const int lane = t & 31;
    const int row0 = blockIdx.x * 128 + warp * 16;

#pragma unroll
    for (int u = 0; u < 4; u++) {
        int id = t + u * 256;
        int r  = id >> 3;
        int c8 = id & 7;
        *(uint4*)&lw[r][c8 * 8] = *(const uint4*)&g_lwh[(size_t)r * OUTC + c8 * 8];
    }
    if (t < OUTC) lb[t] = lin_b[t];
    __syncthreads();

    wmma::fragment<wmma::accumulator, 16, 16, 16, float> acc[4];
#pragma unroll
    for (int j = 0; j < 4; j++) wmma::fill_fragment(acc[j], 0.0f);

#pragma unroll
    for (int k = 0; k < 8; k++) {
        wmma::fragment<wmma::matrix_a, 16, 16, 16, __half, wmma::row_major> af;
        wmma::load_matrix_sync(af, &g_aggh[(size_t)row0 * HC + k * 16], HC);
#pragma unroll
        for (int j = 0; j < 4; j++) {
            wmma::fragment<wmma::matrix_b, 16, 16, 16, __half, wmma::row_major> bf;
            wmma::load_matrix_sync(bf, &lw[k * 16][j * 16], 72);
            wmma::mma_sync(acc[j], af, bf, acc[j]);
        }
    }

    const int lrow = lane >> 1;
    const int lhp  = lane & 1;
    const int grow = row0 + lrow;
#pragma unroll
    for (int j = 0; j < 4; j++) {
        wmma::store_matrix_sync(&stage[warp][0][0], acc[j], 20, wmma::mem_row_major);
        __syncwarp();
        if (grow < NN) {
            int cb = j * 16 + lhp * 8;
            const float* sp = &stage[warp][lrow][lhp * 8];
            float4 o0 = make_float4(sp[0] + lb[cb],     sp[1] + lb[cb + 1],
                                    sp[2] + lb[cb + 2], sp[3] + lb[cb + 3]);
            float4 o1 = make_float4(sp[4] + lb[cb + 4], sp[5] + lb[cb + 5],
                                    sp[6] + lb[cb + 6], sp[7] + lb[cb + 7]);
            *(float4*)&out[(size_t)grow * OUTC + cb]     = o0;
            *(float4*)&out[(size_t)grow * OUTC + cb + 4] = o1;
        }
        __syncwarp();
    }
}

// ---------------- launch ------------------------------------------------------
extern "C" void kernel_launch(void* const* d_in, const int* in_sizes, int n_in,
                              void* d_out, int out_size) {
    const float* x       = (const float*)d_in[0];
    const int*   eidx    = (const int*)d_in[1];
    const float* W       = (const float*)d_in[2];
    const float* att_src = (const float*)d_in[3];
    const float* att_dst = (const float*)d_in[4];
    const float* bias    = (const float*)d_in[5];
    const float* lin_W   = (const float*)d_in[6];
    const float* lin_b   = (const float*)d_in[7];
    float*       out     = (float*)d_out;

    k_cvt    <<<(NN * INC / 8 + 255) / 256, 256>>>(x, W, lin_W);   // 0 (+deg init)
    k_hist   <<<(EE / 4 + 255) / 256, 256>>>(eidx);                // 1
    k_scanA  <<<SCAN_BLKS, 256>>>();                               // 2
    k_gemm1t <<<(NN + 63) / 64, 256>>>(att_src, att_dst);          // 3  <- profiled
    k_prep   <<<SCAN_BLKS, 256>>>();                               // 4
    k_scatter<<<(EE / 4 + 255) / 256, 256>>>(eidx);                // 5
    k_aggr   <<<(NN * 32 + 255) / 256, 256>>>(bias);               // 6
    k_out2   <<<(NPAD / 128), 256>>>(lin_b, out);                  // 7
}